// round 14
// baseline (speedup 1.0000x reference)
#include <cuda_runtime.h>

// QConv2d: new_rho[b] = V * rho[b] * V^T,  V = kron(uc[:,2:4], ux, uy) (256x128).
// Channel insertion is a pure +128 index shift. Factorization:
//   M2 = (I2 (x) ux (x) uy) rho (I2 (x) ux (x) uy)^T
//   out block (g,g') = sum_{f,f'} c[g,f] c[g',f'] * M2 block (f,f')
// f32x2 arithmetic throughout. Stage2+combine pipelined in 2 row-chunks so
// global stores overlap the second chunk's compute instead of bursting at the end.
// One CTA per batch, 512 threads, 2 CTAs/SM, single wave.

#define SSTR 132   // row stride (floats): float2/float4 accesses conflict-free

typedef unsigned long long u64;

static constexpr int XBUF_F     = 128 * SSTR;              // Xbuf: [64][SSTR]
static constexpr int TAB_F      = 192 * SSTR;              // float offset of tables
static constexpr int SMEM_BYTES = TAB_F * 4 + 168 * 8;     // 102,720 B

__device__ __forceinline__ u64 ffma2(u64 a, u64 b, u64 c) {
    u64 d; asm("fma.rn.f32x2 %0, %1, %2, %3;" : "=l"(d) : "l"(a), "l"(b), "l"(c)); return d;
}
__device__ __forceinline__ u64 fmul2(u64 a, u64 b) {
    u64 d; asm("mul.rn.f32x2 %0, %1, %2;" : "=l"(d) : "l"(a), "l"(b)); return d;
}
__device__ __forceinline__ u64 bc2(float s) {
    u64 d; asm("mov.b64 %0, {%1, %1};" : "=l"(d) : "f"(s)); return d;
}
__device__ __forceinline__ u64 pk2(float lo, float hi) {
    u64 d; asm("mov.b64 %0, {%1, %2};" : "=l"(d) : "f"(lo), "f"(hi)); return d;
}

__global__ void __launch_bounds__(512, 2)
qconv_kernel(const float* __restrict__ rho_g,
             const float* __restrict__ ux_g,
             const float* __restrict__ uy_g,
             const float* __restrict__ uc_g,
             float* __restrict__ out_g)
{
    extern __shared__ float sm[];
    float* __restrict__ Ssh  = sm;                            // [128][SSTR]
    float* __restrict__ Xbuf = sm + XBUF_F;                   // [64][SSTR]
    u64*   __restrict__ TB   = reinterpret_cast<u64*>(sm + TAB_F);
    u64*   __restrict__ UyB  = TB;        // [64]  (uy[l][j], uy[l][j])       at l*8+j
    u64*   __restrict__ UxB  = TB + 64;   // [64]  (ux[k][i], ux[k][i])       at k*8+i
    u64*   __restrict__ UyT  = TB + 128;  // [32]  (uy[2l2][j], uy[2l2+1][j]) at j*4+l2
    u64*   __restrict__ UcB  = TB + 160;  // [8]   (c[g][f], c[g][f])         at g*2+f

    const int tid = threadIdx.x;
    const int b   = blockIdx.x;

    if (tid < 64) {
        UyB[tid] = bc2(uy_g[tid]);
        UxB[tid] = bc2(ux_g[tid]);
    } else if (tid < 96) {
        int t = tid - 64, j = t >> 2, l2 = t & 3;
        UyT[t] = pk2(uy_g[(2 * l2) * 8 + j], uy_g[(2 * l2 + 1) * 8 + j]);
    } else if (tid < 104) {
        int t = tid - 96;
        UcB[t] = bc2(uc_g[(t >> 1) * 4 + 2 + (t & 1)]);
    }

    // Load rho[b] (128x128 fp32), float4 coalesced.
    {
        const float4* __restrict__ src =
            reinterpret_cast<const float4*>(rho_g) + (size_t)b * 4096;
        #pragma unroll
        for (int it = 0; it < 8; it++) {
            int idx = tid + it * 512;
            int row = idx >> 5;
            int c4  = idx & 31;
            *reinterpret_cast<float4*>(Ssh + row * SSTR + c4 * 4) = src[idx];
        }
    }
    __syncthreads();

    // ---------- Stage 1: left (ux (x) uy) per COLUMN-PAIR, in place, f32x2 ----------
    {
        const int cp  = tid & 63;          // column pair (cols 2cp, 2cp+1)
        const int fh  = (tid >> 6) & 1;    // 64-row half
        const int sub = tid >> 7;          // 0..3
        float* colp = Ssh + (fh * 64) * SSTR + 2 * cp;

        // Y pass: sub owns i-groups {2sub, 2sub+1}; in-place safe per group.
        #pragma unroll
        for (int g = 0; g < 2; g++) {
            int i = sub * 2 + g;
            u64 v[8];
            #pragma unroll
            for (int j = 0; j < 8; j++)
                v[j] = *reinterpret_cast<const u64*>(colp + (i * 8 + j) * SSTR);
            #pragma unroll
            for (int l = 0; l < 8; l++) {
                u64 acc = fmul2(UyB[l * 8], v[0]);
                #pragma unroll
                for (int j = 1; j < 8; j++) acc = ffma2(UyB[l * 8 + j], v[j], acc);
                *reinterpret_cast<u64*>(colp + (i * 8 + l) * SSTR) = acc;
            }
        }
        __syncthreads();

        // X pass: sub owns l in {2sub, 2sub+1}; preload t before writes.
        #pragma unroll
        for (int li = 0; li < 2; li++) {
            int l = sub * 2 + li;
            u64 t[8];
            #pragma unroll
            for (int i = 0; i < 8; i++)
                t[i] = *reinterpret_cast<const u64*>(colp + (i * 8 + l) * SSTR);
            #pragma unroll
            for (int k = 0; k < 8; k++) {
                u64 acc = fmul2(UxB[k * 8], t[0]);
                #pragma unroll
                for (int i = 1; i < 8; i++) acc = ffma2(UxB[k * 8 + i], t[i], acc);
                *reinterpret_cast<u64*>(colp + (k * 8 + l) * SSTR) = acc;
            }
        }
    }
    __syncthreads();

    // ---------- Stage 2 + combine, pipelined in 2 chunks of 32 kl-pairs ----------
    // Chunk c: M1 rows [32c,32c+32) u [64+32c,64+32c+32)  ->  out kl in [32c,32c+32).
    const int rl   = tid & 63;                       // local row 0..63 within chunk
    const int fh2  = (tid >> 6) & 1;                 // 64-col half
    const int sub2 = tid >> 7;                       // 0..3
    u64 cg[8];
    #pragma unroll
    for (int q = 0; q < 8; q++) cg[q] = UcB[q];

    float* __restrict__ Y = out_g + (size_t)b * 65536;

    #pragma unroll
    for (int c = 0; c < 2; c++) {
        const int row = 32 * c + rl + ((rl >> 5) << 5);   // rl<32: 32c+rl ; else 64+32c+(rl-32)
        float* rowp = Ssh + row * SSTR + fh2 * 64;

        // s2Y(c): sub2 owns i-groups {2sub2, 2sub2+1}; in-place per group.
        #pragma unroll
        for (int g = 0; g < 2; g++) {
            int i = sub2 * 2 + g;
            float4 va = *reinterpret_cast<const float4*>(rowp + i * 8);
            float4 vb = *reinterpret_cast<const float4*>(rowp + i * 8 + 4);
            u64 bv[8] = {bc2(va.x), bc2(va.y), bc2(va.z), bc2(va.w),
                         bc2(vb.x), bc2(vb.y), bc2(vb.z), bc2(vb.w)};
            u64 a2[4];
            #pragma unroll
            for (int l2 = 0; l2 < 4; l2++) {
                u64 acc = fmul2(UyT[l2], bv[0]);
                #pragma unroll
                for (int j = 1; j < 8; j++) acc = ffma2(UyT[j * 4 + l2], bv[j], acc);
                a2[l2] = acc;
            }
            ulonglong2 s0; s0.x = a2[0]; s0.y = a2[1];
            ulonglong2 s1; s1.x = a2[2]; s1.y = a2[3];
            *reinterpret_cast<ulonglong2*>(rowp + i * 8)     = s0;
            *reinterpret_cast<ulonglong2*>(rowp + i * 8 + 4) = s1;
        }
        __syncthreads();

        // s2X(c): sub2 owns l-pair {2sub2, 2sub2+1}; writes to Xbuf (no aliasing).
        {
            float* xrow = Xbuf + rl * SSTR + fh2 * 64;
            u64 t[8];
            #pragma unroll
            for (int i = 0; i < 8; i++)
                t[i] = *reinterpret_cast<const u64*>(rowp + i * 8 + 2 * sub2);
            #pragma unroll
            for (int k = 0; k < 8; k++) {
                u64 acc = fmul2(UxB[k * 8], t[0]);
                #pragma unroll
                for (int i = 1; i < 8; i++) acc = ffma2(UxB[k * 8 + i], t[i], acc);
                *reinterpret_cast<u64*>(xrow + k * 8 + 2 * sub2) = acc;
            }
        }
        __syncthreads();

        // combine(c): 512 positions (klc x s4), one per thread; stores issue now
        // and drain while the next chunk computes.
        {
            int s4  = tid & 15;
            int klc = tid >> 4;                    // 0..31
            int kl  = 32 * c + klc;

            const float* p0 = Xbuf + klc * SSTR + s4 * 4;          // f = 0
            const float* p1 = Xbuf + (32 + klc) * SSTR + s4 * 4;   // f = 1
            ulonglong2 x00 = *reinterpret_cast<const ulonglong2*>(p0);
            ulonglong2 x01 = *reinterpret_cast<const ulonglong2*>(p0 + 64);
            ulonglong2 x10 = *reinterpret_cast<const ulonglong2*>(p1);
            ulonglong2 x11 = *reinterpret_cast<const ulonglong2*>(p1 + 64);

            #pragma unroll
            for (int g = 0; g < 4; g++) {
                u64 g0 = cg[g * 2], g1 = cg[g * 2 + 1];
                u64 e0a = ffma2(g1, x10.x, fmul2(g0, x00.x));
                u64 e0b = ffma2(g1, x10.y, fmul2(g0, x00.y));
                u64 e1a = ffma2(g1, x11.x, fmul2(g0, x01.x));
                u64 e1b = ffma2(g1, x11.y, fmul2(g0, x01.y));
                #pragma unroll
                for (int gp = 0; gp < 4; gp++) {
                    u64 d0 = cg[gp * 2], d1 = cg[gp * 2 + 1];
                    ulonglong2 o;
                    o.x = ffma2(d1, e1a, fmul2(d0, e0a));
                    o.y = ffma2(d1, e1b, fmul2(d0, e0b));
                    *reinterpret_cast<ulonglong2*>(
                        Y + (size_t)(g * 64 + kl) * 256 + gp * 64 + s4 * 4) = o;
                }
            }
        }
        // Barrier protecting Xbuf reuse comes from the top of the next chunk's
        // s2Y sync; for c=1 the kernel simply ends.
        if (c == 0) __syncthreads();
    }
}

extern "C" void kernel_launch(void* const* d_in, const int* in_sizes, int n_in,
                              void* d_out, int out_size)
{
    const float* rho = (const float*)d_in[0];
    const float* ux  = (const float*)d_in[1];
    const float* uy  = (const float*)d_in[2];
    const float* uc  = (const float*)d_in[3];
    float* out = (float*)d_out;

    const int nb = in_sizes[0] / (128 * 128);   // 256 batches

    cudaFuncSetAttribute(qconv_kernel,
                         cudaFuncAttributeMaxDynamicSharedMemorySize, SMEM_BYTES);
    qconv_kernel<<<nb, 512, SMEM_BYTES>>>(rho, ux, uy, uc, out);
}

// round 15
// speedup vs baseline: 1.1870x; 1.1870x over previous
#include <cuda_runtime.h>

// QConv2d: new_rho[b] = V * rho[b] * V^T,  V = kron(uc[:,2:4], ux, uy) (256x128).
// Channel insertion is a pure +128 index shift. Factorization:
//   M2 = (I2 (x) ux (x) uy) rho (I2 (x) ux (x) uy)^T   -- in-place, 68 KB smem
//   out block (g,g') = sum_{f,f'} c[g,f] c[g',f'] * M2 block (f,f')
// Stages 1/2 identical to the proven 25us kernel. Epilogue: combine writes
// output-ordered staging in smem; TMA bulk stores (cp.async.bulk S->G) drain
// asynchronously, double-buffered, removing per-thread STG issue cost.
// One CTA per batch, 512 threads, 2 CTAs/SM, single wave.

#define SSTR 132   // buffer row stride: float4 accesses conflict-free (132%32=4)

static constexpr int STAGE_F     = 128 * SSTR;        // staging: 2 x 4096 floats
static constexpr int UY_OFF      = STAGE_F + 8192;
static constexpr int UX_OFF      = UY_OFF + 64;
static constexpr int UC_OFF      = UX_OFF + 64;
static constexpr int SMEM_FLOATS = UC_OFF + 8;
static constexpr int SMEM_BYTES  = SMEM_FLOATS * 4;   // 100,896 B -> 2 CTAs/SM

__device__ __forceinline__ unsigned smem_u32(const void* p) {
    unsigned a;
    asm("{ .reg .u64 t; cvta.to.shared.u64 t, %1; cvt.u32.u64 %0, t; }"
        : "=r"(a) : "l"(p));
    return a;
}

__global__ void __launch_bounds__(512, 2)
qconv_kernel(const float* __restrict__ rho_g,
             const float* __restrict__ ux_g,
             const float* __restrict__ uy_g,
             const float* __restrict__ uc_g,
             float* __restrict__ out_g)
{
    extern __shared__ float sm[];
    float* __restrict__ Ssh = sm;             // [128][SSTR] : rho -> M1 -> M2
    float* __restrict__ Stg = sm + STAGE_F;   // staging ring: 2 x [4][256]x4g
    float* __restrict__ Uy  = sm + UY_OFF;
    float* __restrict__ Ux  = sm + UX_OFF;
    float* __restrict__ Uc2 = sm + UC_OFF;    // Uc2[g*2+f] = uc[g][2+f]

    const int tid = threadIdx.x;
    const int b   = blockIdx.x;

    if (tid < 64) {
        Uy[tid] = uy_g[tid];
        Ux[tid] = ux_g[tid];
    } else if (tid < 72) {
        int t = tid - 64;
        Uc2[t] = uc_g[(t >> 1) * 4 + 2 + (t & 1)];
    }

    // Load rho[b] (128x128 fp32), float4 coalesced, into strided buffer.
    {
        const float4* __restrict__ src =
            reinterpret_cast<const float4*>(rho_g) + (size_t)b * 4096;
        #pragma unroll
        for (int it = 0; it < 8; it++) {
            int idx = tid + it * 512;
            int row = idx >> 5;
            int c4  = idx & 31;
            *reinterpret_cast<float4*>(Ssh + row * SSTR + c4 * 4) = src[idx];
        }
    }
    __syncthreads();

    const int lane = tid & 127;         // column r (stage 1) / row m (stage 2)
    const int fh   = (tid >> 7) & 1;    // f (or f') half — warp-uniform
    const int sub  = tid >> 8;          // sibling split — warp-uniform

    // ---------- Stage 1: left transform (ux (x) uy) per column, in place ----------
    {
        float* col = Ssh + (fh * 64) * SSTR + lane;

        // Y pass: sibling owns i-groups sub*4..sub*4+3 (disjoint rows, in-place safe)
        #pragma unroll
        for (int ii = 0; ii < 4; ii++) {
            int i = sub * 4 + ii;
            float v[8];
            #pragma unroll
            for (int j = 0; j < 8; j++) v[j] = col[(i * 8 + j) * SSTR];
            #pragma unroll
            for (int l = 0; l < 8; l++) {
                float acc = Uy[l * 8] * v[0];
                #pragma unroll
                for (int j = 1; j < 8; j++) acc = fmaf(Uy[l * 8 + j], v[j], acc);
                col[(i * 8 + l) * SSTR] = acc;
            }
        }
        __syncthreads();

        // X pass: sibling owns l = sub*4..sub*4+3 (positions (i*8+l) disjoint per l)
        #pragma unroll
        for (int ll = 0; ll < 4; ll++) {
            int l = sub * 4 + ll;
            float t[8];
            #pragma unroll
            for (int i = 0; i < 8; i++) t[i] = col[(i * 8 + l) * SSTR];
            #pragma unroll
            for (int k = 0; k < 8; k++) {
                float acc = Ux[k * 8] * t[0];
                #pragma unroll
                for (int i = 1; i < 8; i++) acc = fmaf(Ux[k * 8 + i], t[i], acc);
                col[(k * 8 + l) * SSTR] = acc;
            }
        }
    }
    __syncthreads();

    // ---------- Stage 2: right transform per row, in place, float4 accesses ----------
    {
        float* rowp = Ssh + lane * SSTR + fh * 64;

        // Y pass: sibling owns i-groups sub*4..sub*4+3
        #pragma unroll
        for (int ii = 0; ii < 4; ii++) {
            int i = sub * 4 + ii;
            float4 va = *reinterpret_cast<const float4*>(rowp + i * 8);
            float4 vb = *reinterpret_cast<const float4*>(rowp + i * 8 + 4);
            float v[8] = {va.x, va.y, va.z, va.w, vb.x, vb.y, vb.z, vb.w};
            float a[8];
            #pragma unroll
            for (int l = 0; l < 8; l++) {
                float acc = Uy[l * 8] * v[0];
                #pragma unroll
                for (int j = 1; j < 8; j++) acc = fmaf(Uy[l * 8 + j], v[j], acc);
                a[l] = acc;
            }
            *reinterpret_cast<float4*>(rowp + i * 8)     = make_float4(a[0], a[1], a[2], a[3]);
            *reinterpret_cast<float4*>(rowp + i * 8 + 4) = make_float4(a[4], a[5], a[6], a[7]);
        }
        __syncthreads();

        // X pass: sibling owns l-quad lq = sub (columns i*8 + sub*4 .. +3)
        {
            const int lq = sub;
            float4 t[8];
            #pragma unroll
            for (int i = 0; i < 8; i++)
                t[i] = *reinterpret_cast<const float4*>(rowp + i * 8 + lq * 4);
            #pragma unroll
            for (int k = 0; k < 8; k++) {
                float u0 = Ux[k * 8];
                float4 o;
                o.x = u0 * t[0].x; o.y = u0 * t[0].y; o.z = u0 * t[0].z; o.w = u0 * t[0].w;
                #pragma unroll
                for (int i = 1; i < 8; i++) {
                    float u = Ux[k * 8 + i];
                    o.x = fmaf(u, t[i].x, o.x);
                    o.y = fmaf(u, t[i].y, o.y);
                    o.z = fmaf(u, t[i].z, o.z);
                    o.w = fmaf(u, t[i].w, o.w);
                }
                *reinterpret_cast<float4*>(rowp + k * 8 + lq * 4) = o;
            }
        }
    }
    __syncthreads();

    // ---------- Combine + TMA bulk store epilogue ----------
    // 16 chunks of 4 output rows (per g). Thread = (g, gph, klc, s4):
    //   g   = tid>>7        output row-block
    //   gph = (tid>>6)&1    owns gp in {2gph, 2gph+1}
    //   klc = (tid>>4)&3    local row within chunk
    //   s4  = tid&15        float4 column within 64-col block
    {
        const int s4  = tid & 15;
        const int klc = (tid >> 4) & 3;
        const int gph = (tid >> 6) & 1;
        const int g   = tid >> 7;
        const float cg0 = Uc2[g * 2], cg1 = Uc2[g * 2 + 1];
        const float d00 = Uc2[(gph * 2) * 2],     d01 = Uc2[(gph * 2) * 2 + 1];
        const float d10 = Uc2[(gph * 2 + 1) * 2], d11 = Uc2[(gph * 2 + 1) * 2 + 1];

        float* __restrict__ Y = out_g + (size_t)b * 65536;
        const unsigned stg_base = smem_u32(Stg);

        #pragma unroll 4
        for (int c = 0; c < 16; c++) {
            // staging[c&1] was consumed by bulk group c-2; wait for it.
            if (c >= 2) {
                if (tid == 0)
                    asm volatile("cp.async.bulk.wait_group 1;" ::: "memory");
                __syncthreads();
            }

            const int kl = c * 4 + klc;
            const float* p0 = Ssh + kl * SSTR + s4 * 4;          // f = 0 row
            const float* p1 = Ssh + (64 + kl) * SSTR + s4 * 4;   // f = 1 row
            float4 x00 = *reinterpret_cast<const float4*>(p0);
            float4 x01 = *reinterpret_cast<const float4*>(p0 + 64);
            float4 x10 = *reinterpret_cast<const float4*>(p1);
            float4 x11 = *reinterpret_cast<const float4*>(p1 + 64);

            float4 e0, e1;                        // combine over f for this g
            e0.x = fmaf(cg1, x10.x, cg0 * x00.x);
            e0.y = fmaf(cg1, x10.y, cg0 * x00.y);
            e0.z = fmaf(cg1, x10.z, cg0 * x00.z);
            e0.w = fmaf(cg1, x10.w, cg0 * x00.w);
            e1.x = fmaf(cg1, x11.x, cg0 * x01.x);
            e1.y = fmaf(cg1, x11.y, cg0 * x01.y);
            e1.z = fmaf(cg1, x11.z, cg0 * x01.z);
            e1.w = fmaf(cg1, x11.w, cg0 * x01.w);

            float* sbuf = Stg + (c & 1) * 4096 + g * 1024 + klc * 256 + s4 * 4;
            float4 o0, o1;                        // combine over f' for two gp
            o0.x = fmaf(d01, e1.x, d00 * e0.x);
            o0.y = fmaf(d01, e1.y, d00 * e0.y);
            o0.z = fmaf(d01, e1.z, d00 * e0.z);
            o0.w = fmaf(d01, e1.w, d00 * e0.w);
            o1.x = fmaf(d11, e1.x, d10 * e0.x);
            o1.y = fmaf(d11, e1.y, d10 * e0.y);
            o1.z = fmaf(d11, e1.z, d10 * e0.z);
            o1.w = fmaf(d11, e1.w, d10 * e0.w);
            *reinterpret_cast<float4*>(sbuf + (gph * 2) * 64)     = o0;
            *reinterpret_cast<float4*>(sbuf + (gph * 2 + 1) * 64) = o1;

            __syncthreads();

            if (tid == 0) {
                asm volatile("fence.proxy.async.shared::cta;" ::: "memory");
                unsigned src = stg_base + ((c & 1) * 4096) * 4;
                #pragma unroll
                for (int gg = 0; gg < 4; gg++) {
                    const float* dst = Y + (size_t)(gg * 64 + c * 4) * 256;
                    asm volatile(
                        "cp.async.bulk.global.shared::cta.bulk_group [%0], [%1], %2;"
                        :: "l"(dst), "r"(src + gg * 4096u), "n"(4096)
                        : "memory");
                }
                asm volatile("cp.async.bulk.commit_group;" ::: "memory");
            }
        }

        // Drain all outstanding bulk stores before the CTA may retire.
        if (tid == 0)
            asm volatile("cp.async.bulk.wait_group 0;" ::: "memory");
    }
}

extern "C" void kernel_launch(void* const* d_in, const int* in_sizes, int n_in,
                              void* d_out, int out_size)
{
    const float* rho = (const float*)d_in[0];
    const float* ux  = (const float*)d_in[1];
    const float* uy  = (const float*)d_in[2];
    const float* uc  = (const float*)d_in[3];
    float* out = (float*)d_out;

    const int nb = in_sizes[0] / (128 * 128);   // 256 batches

    cudaFuncSetAttribute(qconv_kernel,
                         cudaFuncAttributeMaxDynamicSharedMemorySize, SMEM_BYTES);
    qconv_kernel<<<nb, 512, SMEM_BYTES>>>(rho, ux, uy, uc, out);
}

// round 16
// speedup vs baseline: 1.4200x; 1.1963x over previous
#include <cuda_runtime.h>

// QConv2d: new_rho[b] = V * rho[b] * V^T,  V = kron(uc[:,2:4], ux, uy) (256x128).
// Channel insertion is a pure +128 index shift. Factorization:
//   M2 = (I2 (x) ux (x) uy) rho (I2 (x) ux (x) uy)^T   -- in-place, 66 KB smem
//   out block (g,g') = sum_{f,f'} c[g,f] c[g',f'] * M2 block (f,f')
// Persistent kernel: 148 CTAs, each pipelines 2 batches with double-buffered
// smem + cp.async prefetch. Batch i+1's load hides under batch i's compute;
// batch i's store burst drains under batch i+1's compute. Per-batch stage code
// is identical to the proven 25us kernel. 512 threads, 1 CTA/SM, single wave.

#define SSTR 132   // buffer row stride: float4 accesses conflict-free (132%32=4)

static constexpr int BUF_F       = 128 * SSTR;        // floats per rho buffer
static constexpr int UY_OFF      = 2 * BUF_F;
static constexpr int UX_OFF      = UY_OFF + 64;
static constexpr int UC_OFF      = UX_OFF + 64;
static constexpr int SMEM_FLOATS = UC_OFF + 8;
static constexpr int SMEM_BYTES  = SMEM_FLOATS * 4;   // 135,712 B -> 1 CTA/SM

__device__ __forceinline__ unsigned smem_u32(const void* p) {
    unsigned a;
    asm("{ .reg .u64 t; cvta.to.shared.u64 t, %1; cvt.u32.u64 %0, t; }"
        : "=r"(a) : "l"(p));
    return a;
}

__device__ __forceinline__ void prefetch_rho(float* buf, const float4* src, int tid) {
    #pragma unroll
    for (int it = 0; it < 8; it++) {
        int idx = tid + it * 512;
        int row = idx >> 5;
        int c4  = idx & 31;
        unsigned d = smem_u32(buf + row * SSTR + c4 * 4);
        asm volatile("cp.async.cg.shared.global [%0], [%1], 16;"
                     :: "r"(d), "l"(src + idx) : "memory");
    }
    asm volatile("cp.async.commit_group;" ::: "memory");
}

// One full batch: stages s1Y, s1X, s2Y, s2X in-place in S, then combine + STG.
// Identical structure to the best-known 25us kernel.
__device__ __forceinline__ void process_batch(
    float* __restrict__ Ssh,
    const float* __restrict__ Uy,
    const float* __restrict__ Ux,
    const float* __restrict__ Uc2,
    float* __restrict__ Y,
    int tid)
{
    const int lane = tid & 127;         // column r (stage 1) / row m (stage 2)
    const int fh   = (tid >> 7) & 1;    // f (or f') half — warp-uniform
    const int sub  = tid >> 8;          // sibling split — warp-uniform

    // ---------- Stage 1: left transform (ux (x) uy) per column, in place ----------
    {
        float* col = Ssh + (fh * 64) * SSTR + lane;

        // Y pass: sibling owns i-groups sub*4..sub*4+3 (disjoint rows, in-place safe)
        #pragma unroll
        for (int ii = 0; ii < 4; ii++) {
            int i = sub * 4 + ii;
            float v[8];
            #pragma unroll
            for (int j = 0; j < 8; j++) v[j] = col[(i * 8 + j) * SSTR];
            #pragma unroll
            for (int l = 0; l < 8; l++) {
                float acc = Uy[l * 8] * v[0];
                #pragma unroll
                for (int j = 1; j < 8; j++) acc = fmaf(Uy[l * 8 + j], v[j], acc);
                col[(i * 8 + l) * SSTR] = acc;
            }
        }
        __syncthreads();

        // X pass: sibling owns l = sub*4..sub*4+3 (positions (i*8+l) disjoint per l)
        #pragma unroll
        for (int ll = 0; ll < 4; ll++) {
            int l = sub * 4 + ll;
            float t[8];
            #pragma unroll
            for (int i = 0; i < 8; i++) t[i] = col[(i * 8 + l) * SSTR];
            #pragma unroll
            for (int k = 0; k < 8; k++) {
                float acc = Ux[k * 8] * t[0];
                #pragma unroll
                for (int i = 1; i < 8; i++) acc = fmaf(Ux[k * 8 + i], t[i], acc);
                col[(k * 8 + l) * SSTR] = acc;
            }
        }
    }
    __syncthreads();

    // ---------- Stage 2: right transform per row, in place, float4 accesses ----------
    {
        float* rowp = Ssh + lane * SSTR + fh * 64;

        // Y pass: sibling owns i-groups sub*4..sub*4+3
        #pragma unroll
        for (int ii = 0; ii < 4; ii++) {
            int i = sub * 4 + ii;
            float4 va = *reinterpret_cast<const float4*>(rowp + i * 8);
            float4 vb = *reinterpret_cast<const float4*>(rowp + i * 8 + 4);
            float v[8] = {va.x, va.y, va.z, va.w, vb.x, vb.y, vb.z, vb.w};
            float a[8];
            #pragma unroll
            for (int l = 0; l < 8; l++) {
                float acc = Uy[l * 8] * v[0];
                #pragma unroll
                for (int j = 1; j < 8; j++) acc = fmaf(Uy[l * 8 + j], v[j], acc);
                a[l] = acc;
            }
            *reinterpret_cast<float4*>(rowp + i * 8)     = make_float4(a[0], a[1], a[2], a[3]);
            *reinterpret_cast<float4*>(rowp + i * 8 + 4) = make_float4(a[4], a[5], a[6], a[7]);
        }
        __syncthreads();

        // X pass: sibling owns l-quad lq = sub (columns i*8 + sub*4 .. +3)
        {
            const int lq = sub;
            float4 t[8];
            #pragma unroll
            for (int i = 0; i < 8; i++)
                t[i] = *reinterpret_cast<const float4*>(rowp + i * 8 + lq * 4);
            #pragma unroll
            for (int k = 0; k < 8; k++) {
                float u0 = Ux[k * 8];
                float4 o;
                o.x = u0 * t[0].x; o.y = u0 * t[0].y; o.z = u0 * t[0].z; o.w = u0 * t[0].w;
                #pragma unroll
                for (int i = 1; i < 8; i++) {
                    float u = Ux[k * 8 + i];
                    o.x = fmaf(u, t[i].x, o.x);
                    o.y = fmaf(u, t[i].y, o.y);
                    o.z = fmaf(u, t[i].z, o.z);
                    o.w = fmaf(u, t[i].w, o.w);
                }
                *reinterpret_cast<float4*>(rowp + k * 8 + lq * 4) = o;
            }
        }
    }
    __syncthreads();

    // ---------- Combine: each M2 float4 read once, fan out to 16 output blocks ----------
    {
        float c[8];
        #pragma unroll
        for (int q = 0; q < 8; q++) c[q] = Uc2[q];

        #pragma unroll
        for (int it = 0; it < 2; it++) {
            int idx = tid + it * 512;          // 1024 (kl, s4) positions
            int s4  = idx & 15;                // float4 index within 64-col block
            int kl  = idx >> 4;                // row within block

            const float* p0 = Ssh + kl * SSTR + s4 * 4;          // f = 0 row
            const float* p1 = Ssh + (64 + kl) * SSTR + s4 * 4;   // f = 1 row
            float4 x00 = *reinterpret_cast<const float4*>(p0);        // f=0,f'=0
            float4 x01 = *reinterpret_cast<const float4*>(p0 + 64);   // f=0,f'=1
            float4 x10 = *reinterpret_cast<const float4*>(p1);        // f=1,f'=0
            float4 x11 = *reinterpret_cast<const float4*>(p1 + 64);   // f=1,f'=1

            #pragma unroll
            for (int g = 0; g < 4; g++) {
                float g0 = c[g * 2], g1 = c[g * 2 + 1];
                float4 e0, e1;                        // combine over f
                e0.x = fmaf(g1, x10.x, g0 * x00.x);
                e0.y = fmaf(g1, x10.y, g0 * x00.y);
                e0.z = fmaf(g1, x10.z, g0 * x00.z);
                e0.w = fmaf(g1, x10.w, g0 * x00.w);
                e1.x = fmaf(g1, x11.x, g0 * x01.x);
                e1.y = fmaf(g1, x11.y, g0 * x01.y);
                e1.z = fmaf(g1, x11.z, g0 * x01.z);
                e1.w = fmaf(g1, x11.w, g0 * x01.w);
                #pragma unroll
                for (int gp = 0; gp < 4; gp++) {
                    float d0 = c[gp * 2], d1 = c[gp * 2 + 1];
                    float4 o;                         // combine over f'
                    o.x = fmaf(d1, e1.x, d0 * e0.x);
                    o.y = fmaf(d1, e1.y, d0 * e0.y);
                    o.z = fmaf(d1, e1.z, d0 * e0.z);
                    o.w = fmaf(d1, e1.w, d0 * e0.w);
                    *reinterpret_cast<float4*>(
                        Y + (size_t)(g * 64 + kl) * 256 + gp * 64 + s4 * 4) = o;
                }
            }
        }
    }
}

__global__ void __launch_bounds__(512, 1)
qconv_kernel(const float* __restrict__ rho_g,
             const float* __restrict__ ux_g,
             const float* __restrict__ uy_g,
             const float* __restrict__ uc_g,
             float* __restrict__ out_g,
             int nb)
{
    extern __shared__ float sm[];
    float* __restrict__ Uy  = sm + UY_OFF;
    float* __restrict__ Ux  = sm + UX_OFF;
    float* __restrict__ Uc2 = sm + UC_OFF;    // Uc2[g*2+f] = uc[g][2+f]

    const int tid = threadIdx.x;
    const int stride = gridDim.x;

    if (tid < 64) {
        Uy[tid] = uy_g[tid];
        Ux[tid] = ux_g[tid];
    } else if (tid < 72) {
        int t = tid - 64;
        Uc2[t] = uc_g[(t >> 1) * 4 + 2 + (t & 1)];
    }

    const float4* __restrict__ rho4 = reinterpret_cast<const float4*>(rho_g);

    // Issue prefetches for this CTA's first two batches immediately.
    int b = blockIdx.x;
    if (b < nb)          prefetch_rho(sm,         rho4 + (size_t)b * 4096,            tid);
    if (b + stride < nb) prefetch_rho(sm + BUF_F, rho4 + (size_t)(b + stride) * 4096, tid);

    int cur = 0;
    for (; b < nb; b += stride, cur ^= 1) {
        // Wait only for THIS batch's buffer; keep the next prefetch in flight.
        if (b + stride < nb)
            asm volatile("cp.async.wait_group 1;" ::: "memory");
        else
            asm volatile("cp.async.wait_group 0;" ::: "memory");
        __syncthreads();

        process_batch(sm + cur * BUF_F, Uy, Ux, Uc2,
                      out_g + (size_t)b * 65536, tid);

        // Prefetch batch b+2*stride into the buffer we just finished reading.
        if (b + 2 * stride < nb) {               // not taken for nb=256, grid=148
            __syncthreads();
            prefetch_rho(sm + cur * BUF_F,
                         rho4 + (size_t)(b + 2 * stride) * 4096, tid);
        }
    }
}

extern "C" void kernel_launch(void* const* d_in, const int* in_sizes, int n_in,
                              void* d_out, int out_size)
{
    const float* rho = (const float*)d_in[0];
    const float* ux  = (const float*)d_in[1];
    const float* uy  = (const float*)d_in[2];
    const float* uc  = (const float*)d_in[3];
    float* out = (float*)d_out;

    const int nb   = in_sizes[0] / (128 * 128);   // 256 batches
    const int grid = nb < 148 ? nb : 148;         // persistent: 1 CTA/SM, 1 wave

    cudaFuncSetAttribute(qconv_kernel,
                         cudaFuncAttributeMaxDynamicSharedMemorySize, SMEM_BYTES);
    qconv_kernel<<<grid, 512, SMEM_BYTES>>>(rho, ux, uy, uc, out, nb);
}